// round 8
// baseline (speedup 1.0000x reference)
#include <cuda_runtime.h>
#include <cuda_bf16.h>

// out[row, :] = W[days[row], :] + bias, D = 1024 floats = 256 float4.
// R3 winner structure + micro-opts:
//  - 16 rows/CTA in 4 batches of 4 (grid 8192), regs kept <=32 (occ 8)
//  - day indices loaded as one int4 broadcast per batch (1 LDG vs 4)
//  - __stcs streaming stores, fully sequential write order (proven best)
static constexpr int D4 = 256;           // 1024 / 4
static constexpr int ROWS_PER_CTA = 16;
static constexpr int BATCH = 4;
static constexpr int NBATCH = ROWS_PER_CTA / BATCH;

__global__ void __launch_bounds__(256, 8)
doy_gather16_kernel(const int4* __restrict__ days4,
                    const float4* __restrict__ W4,
                    const float4* __restrict__ b4,
                    float4* __restrict__ out4)
{
    const int d4   = threadIdx.x;                 // column (float4 index)
    const int row0 = blockIdx.x * ROWS_PER_CTA;

    const float4 b = __ldg(b4 + d4);              // once per thread

    float4* op = out4 + (size_t)row0 * D4 + d4;

#pragma unroll
    for (int batch = 0; batch < NBATCH; ++batch) {
        // one 16B broadcast load = 4 day indices
        const int4 dy = __ldg(days4 + (row0 >> 2) + batch);

        float4 w0 = __ldg(W4 + (size_t)dy.x * D4 + d4);
        float4 w1 = __ldg(W4 + (size_t)dy.y * D4 + d4);
        float4 w2 = __ldg(W4 + (size_t)dy.z * D4 + d4);
        float4 w3 = __ldg(W4 + (size_t)dy.w * D4 + d4);

        w0.x += b.x; w0.y += b.y; w0.z += b.z; w0.w += b.w;
        w1.x += b.x; w1.y += b.y; w1.z += b.z; w1.w += b.w;
        w2.x += b.x; w2.y += b.y; w2.z += b.z; w2.w += b.w;
        w3.x += b.x; w3.y += b.y; w3.z += b.z; w3.w += b.w;

        __stcs(op + (size_t)(batch * BATCH + 0) * D4, w0);
        __stcs(op + (size_t)(batch * BATCH + 1) * D4, w1);
        __stcs(op + (size_t)(batch * BATCH + 2) * D4, w2);
        __stcs(op + (size_t)(batch * BATCH + 3) * D4, w3);
    }
}

extern "C" void kernel_launch(void* const* d_in, const int* in_sizes, int n_in,
                              void* d_out, int out_size)
{
    const int4*   days4 = (const int4*)d_in[0];
    const float4* W4    = (const float4*)d_in[1];
    const float4* b4    = (const float4*)d_in[2];
    float4*       out4  = (float4*)d_out;

    const int n_rows = in_sizes[0];                 // 131072 (divisible by 16)
    const int n_cta  = n_rows / ROWS_PER_CTA;       // 8192

    doy_gather16_kernel<<<n_cta, 256>>>(days4, W4, b4, out4);
}